// round 7
// baseline (speedup 1.0000x reference)
#include <cuda_runtime.h>
#include <math.h>
#include <float.h>

#define B_DIM  256
#define T_DIM  150
#define J_DIM  25
#define FEAT   9
#define NACC   7                        // S1..S4, Vs2, Vs3, Vs4
#define SPLIT  3
#define TCHUNK (T_DIM / SPLIT)          // 50 timesteps per block
#define TPB    250                      // 5 threads per timestep
#define CHAINS 5                        // joints per thread (p, p+5, ..., p+20)
#define ITEMS  (TCHUNK * J_DIM)         // 1250
#define OUTB   (J_DIM * FEAT)           // 225
#define PARTB  (J_DIM * NACC)           // 175

__device__ float    g_scratch[B_DIM][SPLIT][PARTB];
__device__ unsigned g_ticket[B_DIM];    // zero-init; self-resetting

__device__ __forceinline__ float asqrt(float x) {
    float r;
    asm("sqrt.approx.f32 %0, %1;" : "=f"(r) : "f"(x));
    return r;
}

__global__ __launch_bounds__(TPB)
void knn_feat_kernel(const float* __restrict__ x, float* __restrict__ out) {
    __shared__ float4 spos[TCHUNK][J_DIM];   // 50*25*16 = 20000 B
    __shared__ float  spart[PARTB];
    __shared__ float  sfin[PARTB];
    __shared__ bool   s_last;

    const int b   = blockIdx.x;
    const int s   = blockIdx.y;
    const int tid = threadIdx.x;

    // cooperative load of 50x25 positions; w slot = |q|^2
    const float* xb = x + ((size_t)b * T_DIM + s * TCHUNK) * (J_DIM * 3);
#pragma unroll
    for (int r = 0; r < 5; ++r) {
        int i = tid + r * TPB;
        float px = xb[3 * i + 0];
        float py = xb[3 * i + 1];
        float pz = xb[3 * i + 2];
        float pp = fmaf(px, px, fmaf(py, py, pz * pz));
        spos[i / J_DIM][i % J_DIM] = make_float4(px, py, pz, pp);
    }
    if (tid < PARTB) spart[tid] = 0.0f;
    __syncthreads();

    const int p = tid % CHAINS;          // joint residue: chains at p + 5c
    const int t = tid / CHAINS;          // 0..49

    // per-chain query constants: g = q.w - 2 p.q ; d^2 = pp + g
    float ax[CHAINS], ay[CHAINS], az[CHAINS], pw[CHAINS];
#pragma unroll
    for (int c = 0; c < CHAINS; ++c) {
        const float4 P = spos[t][p + 5 * c];
        ax[c] = -2.0f * P.x;
        ay[c] = -2.0f * P.y;
        az[c] = -2.0f * P.z;
        pw[c] = P.w;
    }

    float m0[CHAINS], m1[CHAINS], m2[CHAINS], m3[CHAINS];
#pragma unroll
    for (int c = 0; c < CHAINS; ++c) {
        m0[c] = FLT_MAX; m1[c] = FLT_MAX; m2[c] = FLT_MAX; m3[c] = FLT_MAX;
    }

#pragma unroll 5
    for (int j = 0; j < J_DIM; ++j) {
        const float4 q = spos[t][j];     // ONE shared load for 5 chains
#pragma unroll
        for (int c = 0; c < CHAINS; ++c) {
            float g = fmaf(az[c], q.z,
                       fmaf(ay[c], q.y,
                        fmaf(ax[c], q.x, q.w)));
            g = (j == p + 5 * c) ? FLT_MAX : g;   // mask self
            float hi;
            hi = fmaxf(g, m0[c]); m0[c] = fminf(g, m0[c]); g = hi;
            hi = fmaxf(g, m1[c]); m1[c] = fminf(g, m1[c]); g = hi;
            hi = fmaxf(g, m2[c]); m2[c] = fminf(g, m2[c]); g = hi;
            m3[c] = fminf(g, m3[c]);
        }
    }

    // epilogue: features per chain, accumulate into per-block partials
#pragma unroll
    for (int c = 0; c < CHAINS; ++c) {
        const float d1 = asqrt(fmaxf(pw[c] + m0[c], 0.0f));
        const float d2 = asqrt(fmaxf(pw[c] + m1[c], 0.0f));
        const float d3 = asqrt(fmaxf(pw[c] + m2[c], 0.0f));
        const float d4 = asqrt(fmaxf(pw[c] + m3[c], 0.0f));

        const float s2 = fabsf(d2 - d1) * 0.70710678118654752f;
        const float a3 = (d1 + d2 + d3) * (1.0f / 3.0f);
        const float e1 = d1 - a3, e2 = d2 - a3, e3 = d3 - a3;
        const float s3 = asqrt(fmaf(e1, e1, fmaf(e2, e2, e3 * e3)) * 0.5f);
        const float a4 = (d1 + d2 + d3 + d4) * 0.25f;
        const float g1 = d1 - a4, g2 = d2 - a4, g3 = d3 - a4, g4 = d4 - a4;
        const float s4 = asqrt(fmaf(g1, g1, fmaf(g2, g2, fmaf(g3, g3, g4 * g4)))
                               * (1.0f / 3.0f));

        const int jj = p + 5 * c;
        atomicAdd(&spart[jj * NACC + 0], d1);
        atomicAdd(&spart[jj * NACC + 1], d2);
        atomicAdd(&spart[jj * NACC + 2], d3);
        atomicAdd(&spart[jj * NACC + 3], d4);
        atomicAdd(&spart[jj * NACC + 4], s2);
        atomicAdd(&spart[jj * NACC + 5], s3);
        atomicAdd(&spart[jj * NACC + 6], s4);
    }
    __syncthreads();

    // publish this split's partial
    if (tid < PARTB) g_scratch[b][s][tid] = spart[tid];
    __threadfence();
    __syncthreads();

    if (tid == 0) {
        unsigned old = atomicAdd(&g_ticket[b], 1u);
        s_last = (old == SPLIT - 1);
        if (s_last) g_ticket[b] = 0;   // self-reset for next graph replay
    }
    __syncthreads();

    if (s_last) {
        __threadfence();
        if (tid < PARTB) {
            float sum = 0.0f;
#pragma unroll
            for (int k = 0; k < SPLIT; ++k)
                sum += g_scratch[b][k][tid];
            sfin[tid] = sum;
        }
        __syncthreads();
        if (tid < OUTB) {
            const int j = tid / FEAT;
            const int f = tid % FEAT;
            const float* a = &sfin[j * NACC];
            const float t1 = a[0], t2 = a[1], t3 = a[2], t4 = a[3];
            float v;
            switch (f) {
                case 0: v = (t1 + t2) * 0.5f;               break;
                case 1: v = a[4];                           break;
                case 2: v = t1;                             break;
                case 3: v = (t1 + t2 + t3) * (1.f / 3.f);   break;
                case 4: v = a[5];                           break;
                case 5: v = t1;                             break;
                case 6: v = (t1 + t2 + t3 + t4) * 0.25f;    break;
                case 7: v = a[6];                           break;
                default: v = t1;                            break;
            }
            out[(size_t)b * OUTB + tid] = v * (1.0f / (float)T_DIM);
        }
    }
}

extern "C" void kernel_launch(void* const* d_in, const int* in_sizes, int n_in,
                              void* d_out, int out_size) {
    const float* x = (const float*)d_in[0];
    float* out = (float*)d_out;
    dim3 grid(B_DIM, SPLIT);
    knn_feat_kernel<<<grid, TPB>>>(x, out);
}

// round 8
// speedup vs baseline: 2.9525x; 2.9525x over previous
#include <cuda_runtime.h>
#include <cuda_fp16.h>
#include <math.h>
#include <float.h>

#define B_DIM  256
#define T_DIM  150
#define J_DIM  25
#define FEAT   9
#define NACC   7                        // S1..S4, Vs2, Vs3, Vs4
#define SPLIT  5
#define TCHUNK (T_DIM / SPLIT)          // 30 timesteps per block
#define NPAIR  (TCHUNK / 2)             // 15 timestep-pairs
#define TPB    (NPAIR * J_DIM)          // 375 threads; thread = (pair, joint)
#define ITEMS  (TCHUNK * J_DIM)         // 750
#define OUTB   (J_DIM * FEAT)           // 225
#define PARTB  (J_DIM * NACC)           // 175

__device__ float    g_scratch[B_DIM][SPLIT][PARTB];
__device__ unsigned g_ticket[B_DIM];    // zero-init; self-resetting

__device__ __forceinline__ float asqrt(float x) {
    float r;
    asm("sqrt.approx.f32 %0, %1;" : "=f"(r) : "f"(x));
    return r;
}

__global__ __launch_bounds__(TPB)
void knn_feat_kernel(const float* __restrict__ x, float* __restrict__ out) {
    // packed positions: [pair][joint] = {x2, y2, z2, pad} (half2 lanes = t, t+15)
    __shared__ uint4 sq[NPAIR][J_DIM];       // 15*25*16 = 6000 B
    __shared__ float spart[PARTB];
    __shared__ float sfin[PARTB];
    __shared__ bool  s_last;

    const int b   = blockIdx.x;
    const int s   = blockIdx.y;
    const int tid = threadIdx.x;

    // build packed half2 SMEM tile
    const float* xb = x + ((size_t)b * T_DIM + s * TCHUNK) * (J_DIM * 3);
#pragma unroll
    for (int r = 0; r < 2; ++r) {
        int i = tid + r * TPB;               // 0..749 : (t, j) item
        int t = i / J_DIM;                   // 0..29
        int j = i % J_DIM;
        int pr = t % NPAIR;                  // pair row
        int hi = t / NPAIR;                  // 0 = lo half, 1 = hi half
        __half hx = __float2half_rn(xb[3 * i + 0]);
        __half hy = __float2half_rn(xb[3 * i + 1]);
        __half hz = __float2half_rn(xb[3 * i + 2]);
        __half* base = (__half*)&sq[pr][j];
        base[0 * 2 + hi] = hx;
        base[1 * 2 + hi] = hy;
        base[2 * 2 + hi] = hz;
    }
    if (tid < PARTB) spart[tid] = 0.0f;
    __syncthreads();

    const int jidx = tid % J_DIM;            // this thread's joint
    const int pr   = tid / J_DIM;            // this thread's timestep pair (0..14)

    // query position (both halves) — one LDS.128
    const uint4 P = sq[pr][jidx];
    const __half2 px = *(const __half2*)&P.x;
    const __half2 py = *(const __half2*)&P.y;
    const __half2 pz = *(const __half2*)&P.z;

    const unsigned inf_bits = 0x7C007C00u;   // (+inf, +inf)
    const __half2 inf2 = *(const __half2*)&inf_bits;

    __half2 m0 = inf2, m1 = inf2, m2 = inf2, m3 = inf2;

#pragma unroll
    for (int j = 0; j < J_DIM; ++j) {
        const uint4 Q = sq[pr][j];           // broadcast LDS.128, feeds 2 candidates
        const __half2 qx = *(const __half2*)&Q.x;
        const __half2 qy = *(const __half2*)&Q.y;
        const __half2 qz = *(const __half2*)&Q.z;

        const __half2 dx = __hsub2(px, qx);
        const __half2 dy = __hsub2(py, qy);
        const __half2 dz = __hsub2(pz, qz);
        __half2 g = __hfma2(dx, dx, __hfma2(dy, dy, __hmul2(dz, dz)));
        g = (j == jidx) ? inf2 : g;          // mask self (both halves)

        __half2 h;
        h = __hmax2(g, m0); m0 = __hmin2(g, m0); g = h;
        h = __hmax2(g, m1); m1 = __hmin2(g, m1); g = h;
        h = __hmax2(g, m2); m2 = __hmin2(g, m2); g = h;
        m3 = __hmin2(g, m3);
    }

    // epilogue: two chains (lo/hi halves), features in fp32, summed
    float S1 = 0.f, S2 = 0.f, S3 = 0.f, S4 = 0.f;
    float V2 = 0.f, V3 = 0.f, V4 = 0.f;

#pragma unroll
    for (int h = 0; h < 2; ++h) {
        const float q0 = h ? __high2float(m0) : __low2float(m0);
        const float q1 = h ? __high2float(m1) : __low2float(m1);
        const float q2 = h ? __high2float(m2) : __low2float(m2);
        const float q3 = h ? __high2float(m3) : __low2float(m3);

        const float d1 = asqrt(q0);
        const float d2 = asqrt(q1);
        const float d3 = asqrt(q2);
        const float d4 = asqrt(q3);

        const float s2 = fabsf(d2 - d1) * 0.70710678118654752f;
        const float a3 = (d1 + d2 + d3) * (1.0f / 3.0f);
        const float e1 = d1 - a3, e2 = d2 - a3, e3 = d3 - a3;
        const float s3 = asqrt(fmaf(e1, e1, fmaf(e2, e2, e3 * e3)) * 0.5f);
        const float a4 = (d1 + d2 + d3 + d4) * 0.25f;
        const float g1 = d1 - a4, g2 = d2 - a4, g3 = d3 - a4, g4 = d4 - a4;
        const float s4 = asqrt(fmaf(g1, g1, fmaf(g2, g2, fmaf(g3, g3, g4 * g4)))
                               * (1.0f / 3.0f));

        S1 += d1; S2 += d2; S3 += d3; S4 += d4;
        V2 += s2; V3 += s3; V4 += s4;
    }

    // combine the 15 threads sharing each joint (SMEM atomics)
    atomicAdd(&spart[jidx * NACC + 0], S1);
    atomicAdd(&spart[jidx * NACC + 1], S2);
    atomicAdd(&spart[jidx * NACC + 2], S3);
    atomicAdd(&spart[jidx * NACC + 3], S4);
    atomicAdd(&spart[jidx * NACC + 4], V2);
    atomicAdd(&spart[jidx * NACC + 5], V3);
    atomicAdd(&spart[jidx * NACC + 6], V4);
    __syncthreads();

    // publish this split's partial
    if (tid < PARTB) g_scratch[b][s][tid] = spart[tid];
    __threadfence();
    __syncthreads();

    if (tid == 0) {
        unsigned old = atomicAdd(&g_ticket[b], 1u);
        s_last = (old == SPLIT - 1);
        if (s_last) g_ticket[b] = 0;   // self-reset for next graph replay
    }
    __syncthreads();

    if (s_last) {
        __threadfence();
        if (tid < PARTB) {
            float sum = 0.0f;
#pragma unroll
            for (int k = 0; k < SPLIT; ++k)
                sum += g_scratch[b][k][tid];
            sfin[tid] = sum;
        }
        __syncthreads();
        if (tid < OUTB) {
            const int j = tid / FEAT;
            const int f = tid % FEAT;
            const float* a = &sfin[j * NACC];
            const float t1 = a[0], t2 = a[1], t3 = a[2], t4 = a[3];
            float v;
            switch (f) {
                case 0: v = (t1 + t2) * 0.5f;               break;
                case 1: v = a[4];                           break;
                case 2: v = t1;                             break;
                case 3: v = (t1 + t2 + t3) * (1.f / 3.f);   break;
                case 4: v = a[5];                           break;
                case 5: v = t1;                             break;
                case 6: v = (t1 + t2 + t3 + t4) * 0.25f;    break;
                case 7: v = a[6];                           break;
                default: v = t1;                            break;
            }
            out[(size_t)b * OUTB + tid] = v * (1.0f / (float)T_DIM);
        }
    }
}

extern "C" void kernel_launch(void* const* d_in, const int* in_sizes, int n_in,
                              void* d_out, int out_size) {
    const float* x = (const float*)d_in[0];
    float* out = (float*)d_out;
    dim3 grid(B_DIM, SPLIT);
    knn_feat_kernel<<<grid, TPB>>>(x, out);
}